// round 2
// baseline (speedup 1.0000x reference)
#include <cuda_runtime.h>

#define NN   100000
#define EE   1600000
#define IND  64
#define OUTD 128
#define SCAN_B 512
#define NBLK 196          // ceil(NN/512)
#define BN_EPS 1e-5f

// ---------------- scratch (static device globals; no allocation) ----------------
__device__ int   g_cnt[NN];
__device__ int   g_off[NN];
__device__ int   g_cur[NN];
__device__ int   g_bsum[256];
__device__ int   g_src[EE];
__device__ float g_dinv[NN];
__device__ float g_xt[(size_t)NN * OUTD];    // x @ W
__device__ float g_base[(size_t)NN * OUTD];  // bias + x @ skip_W, then overwritten with pre-BN out
__device__ float g_sum[OUTD];
__device__ float g_sq[OUTD];
__device__ float g_mean[OUTD];
__device__ float g_istd[OUTD];

// ---------------- f32x2 helpers ----------------
__device__ __forceinline__ void fma2(unsigned long long& d, unsigned long long a, unsigned long long b) {
    asm("fma.rn.f32x2 %0, %1, %2, %0;" : "+l"(d) : "l"(a), "l"(b));
}
__device__ __forceinline__ unsigned long long dup2(float x) {
    unsigned long long r;
    asm("mov.b64 %0, {%1, %1};" : "=l"(r) : "f"(x));
    return r;
}
__device__ __forceinline__ float2 unpk(unsigned long long v) {
    float2 r;
    asm("mov.b64 {%0, %1}, %2;" : "=f"(r.x), "=f"(r.y) : "l"(v));
    return r;
}

// ---------------- kernels ----------------
__global__ void k_zero() {
    int i = blockIdx.x * blockDim.x + threadIdx.x;
    if (i < NN) g_cnt[i] = 0;
    if (i < OUTD) { g_sum[i] = 0.f; g_sq[i] = 0.f; }
}

__global__ void k_hist(const int* __restrict__ ei) {
    int e = blockIdx.x * blockDim.x + threadIdx.x;
    if (e < EE) atomicAdd(&g_cnt[ei[EE + e]], 1);
}

__global__ void k_scan1() {
    __shared__ int s[SCAN_B];
    int t = threadIdx.x;
    int i = blockIdx.x * SCAN_B + t;
    int c = (i < NN) ? g_cnt[i] : 0;
    if (i < NN) g_dinv[i] = rsqrtf((float)(c + 1));   // +1 self-loop
    s[t] = c;
    __syncthreads();
    for (int o = 1; o < SCAN_B; o <<= 1) {
        int v = (t >= o) ? s[t - o] : 0;
        __syncthreads();
        s[t] += v;
        __syncthreads();
    }
    if (i < NN) g_off[i] = s[t] - c;                   // local exclusive
    if (t == SCAN_B - 1) g_bsum[blockIdx.x] = s[t];    // block total
}

__global__ void k_scan2() {
    __shared__ int s[256];
    int t = threadIdx.x;
    int v = (t < NBLK) ? g_bsum[t] : 0;
    s[t] = v;
    __syncthreads();
    for (int o = 1; o < 256; o <<= 1) {
        int u = (t >= o) ? s[t - o] : 0;
        __syncthreads();
        s[t] += u;
        __syncthreads();
    }
    if (t < NBLK) g_bsum[t] = s[t] - v;                // exclusive block bases
}

__global__ void k_scan3() {
    int t = threadIdx.x;
    int i = blockIdx.x * SCAN_B + t;
    if (i < NN) {
        int o = g_off[i] + g_bsum[blockIdx.x];
        g_off[i] = o;
        g_cur[i] = o;
    }
}

__global__ void k_scatter(const int* __restrict__ ei) {
    int e = blockIdx.x * blockDim.x + threadIdx.x;
    if (e < EE) {
        int c = ei[EE + e];
        int p = atomicAdd(&g_cur[c], 1);
        g_src[p] = ei[e];
    }
}

// GEMM: tile 64 rows x 128 cols per block; blockIdx.y: 0 -> W (g_xt), 1 -> skip_W (g_base = bias + x@S)
// 256 threads, each: 8 rows x 4 cols, row-pairs packed as f32x2.
// X tile staged in static smem; W streamed from global (L1-resident after first touch).
__global__ __launch_bounds__(256) void k_gemm(const float* __restrict__ x,
                                              const float* __restrict__ W,
                                              const float* __restrict__ S,
                                              const float* __restrict__ bias) {
    __shared__ float sX[IND * 68];   // [k*68 + r], 64x64 tile, pad 68 to cut STS conflicts

    const float* Wsrc = blockIdx.y ? S : W;
    int tid = threadIdx.x;
    int row0 = blockIdx.x * 64;

    for (int idx = tid; idx < 64 * IND; idx += 256) {
        int r = idx >> 6, k = idx & 63;
        int row = row0 + r;
        sX[k * 68 + r] = (row < NN) ? x[(size_t)row * IND + k] : 0.f;
    }
    __syncthreads();

    int cg = tid & 31, rg = tid >> 5;
    int cbase = cg * 4;

    unsigned long long acc[4][4];
#pragma unroll
    for (int a = 0; a < 4; a++)
#pragma unroll
        for (int b = 0; b < 4; b++) acc[a][b] = 0ull;

#pragma unroll 4
    for (int k = 0; k < IND; k++) {
        ulonglong2 xa = *(const ulonglong2*)(sX + k * 68 + rg * 8);
        ulonglong2 xb = *(const ulonglong2*)(sX + k * 68 + rg * 8 + 4);
        float4 wv = __ldg((const float4*)(Wsrc + k * OUTD + cbase));
        unsigned long long w0 = dup2(wv.x), w1 = dup2(wv.y), w2 = dup2(wv.z), w3 = dup2(wv.w);
        fma2(acc[0][0], xa.x, w0); fma2(acc[0][1], xa.x, w1); fma2(acc[0][2], xa.x, w2); fma2(acc[0][3], xa.x, w3);
        fma2(acc[1][0], xa.y, w0); fma2(acc[1][1], xa.y, w1); fma2(acc[1][2], xa.y, w2); fma2(acc[1][3], xa.y, w3);
        fma2(acc[2][0], xb.x, w0); fma2(acc[2][1], xb.x, w1); fma2(acc[2][2], xb.x, w2); fma2(acc[2][3], xb.x, w3);
        fma2(acc[3][0], xb.y, w0); fma2(acc[3][1], xb.y, w1); fma2(acc[3][2], xb.y, w2); fma2(acc[3][3], xb.y, w3);
    }

    float4 b4 = make_float4(0.f, 0.f, 0.f, 0.f);
    if (blockIdx.y) b4 = *(const float4*)&bias[cbase];
    float* dst = blockIdx.y ? g_base : g_xt;

#pragma unroll
    for (int rp = 0; rp < 4; rp++) {
        float2 p0 = unpk(acc[rp][0]), p1 = unpk(acc[rp][1]), p2 = unpk(acc[rp][2]), p3 = unpk(acc[rp][3]);
        int r0 = row0 + rg * 8 + rp * 2;
        if (r0 < NN) {
            float4 v = make_float4(p0.x + b4.x, p1.x + b4.y, p2.x + b4.z, p3.x + b4.w);
            *(float4*)&dst[(size_t)r0 * OUTD + cbase] = v;
        }
        if (r0 + 1 < NN) {
            float4 v = make_float4(p0.y + b4.x, p1.y + b4.y, p2.y + b4.z, p3.y + b4.w);
            *(float4*)&dst[(size_t)(r0 + 1) * OUTD + cbase] = v;
        }
    }
}

// Aggregation: one warp per node (32 nodes / 1024-thread block), fused BN partial stats.
__global__ __launch_bounds__(1024) void k_aggr() {
    __shared__ float s_sum[OUTD];
    __shared__ float s_sq[OUTD];
    int t = threadIdx.x;
    if (t < OUTD) { s_sum[t] = 0.f; s_sq[t] = 0.f; }
    __syncthreads();

    int node = blockIdx.x * 32 + (t >> 5);
    int lane = t & 31;

    float di = g_dinv[node];
    float4 a = ((const float4*)&g_xt[(size_t)node * OUTD])[lane];
    float4 acc = make_float4(a.x * di, a.y * di, a.z * di, a.w * di);  // self-loop term

    int o = g_off[node];
    int c = g_cnt[node];
    int j = 0;
    for (; j + 1 < c; j += 2) {
        int s0 = g_src[o + j], s1 = g_src[o + j + 1];
        float d0 = g_dinv[s0], d1 = g_dinv[s1];
        float4 v0 = ((const float4*)&g_xt[(size_t)s0 * OUTD])[lane];
        float4 v1 = ((const float4*)&g_xt[(size_t)s1 * OUTD])[lane];
        acc.x += d0 * v0.x + d1 * v1.x;
        acc.y += d0 * v0.y + d1 * v1.y;
        acc.z += d0 * v0.z + d1 * v1.z;
        acc.w += d0 * v0.w + d1 * v1.w;
    }
    if (j < c) {
        int s0 = g_src[o + j];
        float d0 = g_dinv[s0];
        float4 v0 = ((const float4*)&g_xt[(size_t)s0 * OUTD])[lane];
        acc.x += d0 * v0.x; acc.y += d0 * v0.y; acc.z += d0 * v0.z; acc.w += d0 * v0.w;
    }

    float4 b = ((const float4*)&g_base[(size_t)node * OUTD])[lane];
    float4 out;
    out.x = b.x + di * acc.x;
    out.y = b.y + di * acc.y;
    out.z = b.z + di * acc.z;
    out.w = b.w + di * acc.w;
    ((float4*)&g_base[(size_t)node * OUTD])[lane] = out;  // in-place pre-BN

    int c4 = lane * 4;
    atomicAdd(&s_sum[c4 + 0], out.x);
    atomicAdd(&s_sum[c4 + 1], out.y);
    atomicAdd(&s_sum[c4 + 2], out.z);
    atomicAdd(&s_sum[c4 + 3], out.w);
    atomicAdd(&s_sq[c4 + 0], out.x * out.x);
    atomicAdd(&s_sq[c4 + 1], out.y * out.y);
    atomicAdd(&s_sq[c4 + 2], out.z * out.z);
    atomicAdd(&s_sq[c4 + 3], out.w * out.w);
    __syncthreads();
    if (t < OUTD) {
        atomicAdd(&g_sum[t], s_sum[t]);
        atomicAdd(&g_sq[t], s_sq[t]);
    }
}

__global__ void k_bnparams() {
    int c = threadIdx.x;
    float m = g_sum[c] * (1.0f / NN);
    float v = g_sq[c] * (1.0f / NN) - m * m;
    g_mean[c] = m;
    g_istd[c] = rsqrtf(v + BN_EPS);
}

__global__ __launch_bounds__(1024) void k_final(const float* __restrict__ gamma,
                                                const float* __restrict__ beta,
                                                float* __restrict__ out) {
    int i = blockIdx.x * 1024 + threadIdx.x;   // over NN*32 float4s
    int c4 = (i & 31) * 4;
    float4 v = ((const float4*)g_base)[i];
    float4 r;
    r.x = fmaxf((v.x - g_mean[c4 + 0]) * g_istd[c4 + 0] * gamma[c4 + 0] + beta[c4 + 0], 0.f);
    r.y = fmaxf((v.y - g_mean[c4 + 1]) * g_istd[c4 + 1] * gamma[c4 + 1] + beta[c4 + 1], 0.f);
    r.z = fmaxf((v.z - g_mean[c4 + 2]) * g_istd[c4 + 2] * gamma[c4 + 2] + beta[c4 + 2], 0.f);
    r.w = fmaxf((v.w - g_mean[c4 + 3]) * g_istd[c4 + 3] * gamma[c4 + 3] + beta[c4 + 3], 0.f);
    ((float4*)out)[i] = r;
}

// ---------------- launch ----------------
extern "C" void kernel_launch(void* const* d_in, const int* in_sizes, int n_in,
                              void* d_out, int out_size) {
    const float* x     = (const float*)d_in[0];
    const int*   ei    = (const int*)d_in[1];
    const float* W     = (const float*)d_in[2];
    const float* bias  = (const float*)d_in[3];
    const float* skw   = (const float*)d_in[4];
    const float* gamma = (const float*)d_in[5];
    const float* beta  = (const float*)d_in[6];
    (void)in_sizes; (void)n_in; (void)out_size;

    k_zero<<<98, 1024>>>();
    k_hist<<<3125, 512>>>(ei);
    k_scan1<<<NBLK, SCAN_B>>>();
    k_scan2<<<1, 256>>>();
    k_scan3<<<NBLK, SCAN_B>>>();
    k_scatter<<<3125, 512>>>(ei);
    k_gemm<<<dim3(1563, 2), 256>>>(x, W, skw, bias);
    k_aggr<<<3125, 1024>>>();
    k_bnparams<<<1, OUTD>>>();
    k_final<<<3125, 1024>>>(gamma, beta, (float*)d_out);
}

// round 3
// speedup vs baseline: 1.1460x; 1.1460x over previous
#include <cuda_runtime.h>
#include <cuda_fp16.h>

#define NN   100000
#define EE   1600000
#define IND  64
#define OUTD 128
#define SCAN_B 512
#define NBLK 196          // ceil(NN/512)
#define BN_EPS 1e-5f
#define HIST_BLKS 6250    // EE / 256
#define GEMM_TILES 1563   // ceil(NN/64)

// ---------------- scratch (static device globals; no allocation) ----------------
__device__ int    g_cnt[NN];
__device__ int    g_off[NN];
__device__ int    g_cur[NN];
__device__ int    g_bsum[NBLK];
__device__ int    g_src[EE];
__device__ float  g_dinv[NN];
__device__ __half g_xt[(size_t)NN * OUTD];    // x @ W  (fp16 messages)
__device__ float  g_base[(size_t)NN * OUTD];  // bias + x @ skip_W -> pre-BN out
__device__ float  g_sum[OUTD];
__device__ float  g_sq[OUTD];

// ---------------- f32x2 helpers ----------------
__device__ __forceinline__ void fma2(unsigned long long& d, unsigned long long a, unsigned long long b) {
    asm("fma.rn.f32x2 %0, %1, %2, %0;" : "+l"(d) : "l"(a), "l"(b));
}
__device__ __forceinline__ unsigned long long dup2(float x) {
    unsigned long long r;
    asm("mov.b64 %0, {%1, %1};" : "=l"(r) : "f"(x));
    return r;
}
__device__ __forceinline__ float2 unpk(unsigned long long v) {
    float2 r;
    asm("mov.b64 {%0, %1}, %2;" : "=f"(r.x), "=f"(r.y) : "l"(v));
    return r;
}

// ---------------- GEMM tile body (64 rows x 128 cols), shared by both fused kernels ----
template<bool HALF_OUT>
__device__ __forceinline__ void gemm_tile(int bx, const float* __restrict__ x,
                                          const float* __restrict__ Wsrc,
                                          const float* __restrict__ bias,
                                          float* sX) {
    int tid = threadIdx.x;
    int row0 = bx * 64;

    for (int idx = tid; idx < 64 * IND; idx += 256) {
        int r = idx >> 6, k = idx & 63;
        int row = row0 + r;
        sX[k * 68 + r] = (row < NN) ? x[(size_t)row * IND + k] : 0.f;
    }
    __syncthreads();

    int cg = tid & 31, rg = tid >> 5;
    int cbase = cg * 4;

    unsigned long long acc[4][4];
#pragma unroll
    for (int a = 0; a < 4; a++)
#pragma unroll
        for (int b = 0; b < 4; b++) acc[a][b] = 0ull;

#pragma unroll 4
    for (int k = 0; k < IND; k++) {
        ulonglong2 xa = *(const ulonglong2*)(sX + k * 68 + rg * 8);
        ulonglong2 xb = *(const ulonglong2*)(sX + k * 68 + rg * 8 + 4);
        float4 wv = __ldg((const float4*)(Wsrc + k * OUTD + cbase));
        unsigned long long w0 = dup2(wv.x), w1 = dup2(wv.y), w2 = dup2(wv.z), w3 = dup2(wv.w);
        fma2(acc[0][0], xa.x, w0); fma2(acc[0][1], xa.x, w1); fma2(acc[0][2], xa.x, w2); fma2(acc[0][3], xa.x, w3);
        fma2(acc[1][0], xa.y, w0); fma2(acc[1][1], xa.y, w1); fma2(acc[1][2], xa.y, w2); fma2(acc[1][3], xa.y, w3);
        fma2(acc[2][0], xb.x, w0); fma2(acc[2][1], xb.x, w1); fma2(acc[2][2], xb.x, w2); fma2(acc[2][3], xb.x, w3);
        fma2(acc[3][0], xb.y, w0); fma2(acc[3][1], xb.y, w1); fma2(acc[3][2], xb.y, w2); fma2(acc[3][3], xb.y, w3);
    }

    float4 b4 = make_float4(0.f, 0.f, 0.f, 0.f);
    if (!HALF_OUT) b4 = *(const float4*)&bias[cbase];

#pragma unroll
    for (int rp = 0; rp < 4; rp++) {
        float2 p0 = unpk(acc[rp][0]), p1 = unpk(acc[rp][1]), p2 = unpk(acc[rp][2]), p3 = unpk(acc[rp][3]);
        int r0 = row0 + rg * 8 + rp * 2;
        if (HALF_OUT) {
            if (r0 < NN) {
                half2 h01 = __float22half2_rn(make_float2(p0.x, p1.x));
                half2 h23 = __float22half2_rn(make_float2(p2.x, p3.x));
                uint2 u; u.x = *(unsigned*)&h01; u.y = *(unsigned*)&h23;
                *(uint2*)(g_xt + (size_t)r0 * OUTD + cbase) = u;
            }
            if (r0 + 1 < NN) {
                half2 h01 = __float22half2_rn(make_float2(p0.y, p1.y));
                half2 h23 = __float22half2_rn(make_float2(p2.y, p3.y));
                uint2 u; u.x = *(unsigned*)&h01; u.y = *(unsigned*)&h23;
                *(uint2*)(g_xt + (size_t)(r0 + 1) * OUTD + cbase) = u;
            }
        } else {
            if (r0 < NN) {
                float4 v = make_float4(p0.x + b4.x, p1.x + b4.y, p2.x + b4.z, p3.x + b4.w);
                *(float4*)&g_base[(size_t)r0 * OUTD + cbase] = v;
            }
            if (r0 + 1 < NN) {
                float4 v = make_float4(p0.y + b4.x, p1.y + b4.y, p2.y + b4.z, p3.y + b4.w);
                *(float4*)&g_base[(size_t)(r0 + 1) * OUTD + cbase] = v;
            }
        }
    }
}

// ---------------- kernels ----------------
__global__ void k_zero() {
    int i = blockIdx.x * blockDim.x + threadIdx.x;
    if (i < NN) g_cnt[i] = 0;
    if (i < OUTD) { g_sum[i] = 0.f; g_sq[i] = 0.f; }
}

// Fused: histogram (blocks [0, HIST_BLKS)) || GEMM x@W -> g_xt fp16 (remaining blocks)
__global__ __launch_bounds__(256) void k_hist_gemmW(const int* __restrict__ ei,
                                                    const float* __restrict__ x,
                                                    const float* __restrict__ W) {
    __shared__ float sX[IND * 68];
    if (blockIdx.x < HIST_BLKS) {
        int e = blockIdx.x * 256 + threadIdx.x;
        if (e < EE) atomicAdd(&g_cnt[ei[EE + e]], 1);
    } else {
        gemm_tile<true>(blockIdx.x - HIST_BLKS, x, W, nullptr, sX);
    }
}

__global__ void k_scan1() {
    __shared__ int s[SCAN_B];
    int t = threadIdx.x;
    int i = blockIdx.x * SCAN_B + t;
    int c = (i < NN) ? g_cnt[i] : 0;
    if (i < NN) g_dinv[i] = rsqrtf((float)(c + 1));   // +1 self-loop
    s[t] = c;
    __syncthreads();
    for (int o = 1; o < SCAN_B; o <<= 1) {
        int v = (t >= o) ? s[t - o] : 0;
        __syncthreads();
        s[t] += v;
        __syncthreads();
    }
    if (i < NN) g_off[i] = s[t] - c;                   // local exclusive
    if (t == SCAN_B - 1) g_bsum[blockIdx.x] = s[t];    // block total
}

// Fused scan2+scan3: each block computes its own base from the block sums.
__global__ void k_scan23() {
    __shared__ int sacc[SCAN_B];
    int t = threadIdx.x;
    int v = (t < NBLK && t < blockIdx.x) ? g_bsum[t] : 0;
    sacc[t] = v;
    __syncthreads();
    for (int o = SCAN_B / 2; o > 0; o >>= 1) {
        if (t < o) sacc[t] += sacc[t + o];
        __syncthreads();
    }
    int base = sacc[0];
    int i = blockIdx.x * SCAN_B + t;
    if (i < NN) {
        int o = g_off[i] + base;
        g_off[i] = o;
        g_cur[i] = o;
    }
}

// Fused: scatter (CSR fill) || GEMM x@skip_W + bias -> g_base fp32
__global__ __launch_bounds__(256) void k_scatter_gemmS(const int* __restrict__ ei,
                                                       const float* __restrict__ x,
                                                       const float* __restrict__ S,
                                                       const float* __restrict__ bias) {
    __shared__ float sX[IND * 68];
    if (blockIdx.x < HIST_BLKS) {
        int e = blockIdx.x * 256 + threadIdx.x;
        if (e < EE) {
            int c = ei[EE + e];
            int p = atomicAdd(&g_cur[c], 1);
            g_src[p] = ei[e];
        }
    } else {
        gemm_tile<false>(blockIdx.x - HIST_BLKS, x, S, bias, sX);
    }
}

// Aggregation: one warp per node, fp16 message gathers, fused BN partial stats.
__global__ __launch_bounds__(1024) void k_aggr() {
    __shared__ float s_sum[OUTD];
    __shared__ float s_sq[OUTD];
    int t = threadIdx.x;
    if (t < OUTD) { s_sum[t] = 0.f; s_sq[t] = 0.f; }
    __syncthreads();

    int node = blockIdx.x * 32 + (t >> 5);
    int lane = t & 31;

    float di = g_dinv[node];
    uint2 ua = ((const uint2*)(g_xt + (size_t)node * OUTD))[lane];
    float2 a01 = __half22float2(*(half2*)&ua.x);
    float2 a23 = __half22float2(*(half2*)&ua.y);
    float4 acc = make_float4(a01.x * di, a01.y * di, a23.x * di, a23.y * di);  // self-loop

    int o = g_off[node];
    int c = g_cnt[node];
    int j = 0;
    for (; j + 1 < c; j += 2) {
        int s0 = g_src[o + j], s1 = g_src[o + j + 1];
        float d0 = g_dinv[s0], d1 = g_dinv[s1];
        uint2 u0 = ((const uint2*)(g_xt + (size_t)s0 * OUTD))[lane];
        uint2 u1 = ((const uint2*)(g_xt + (size_t)s1 * OUTD))[lane];
        float2 v001 = __half22float2(*(half2*)&u0.x);
        float2 v023 = __half22float2(*(half2*)&u0.y);
        float2 v101 = __half22float2(*(half2*)&u1.x);
        float2 v123 = __half22float2(*(half2*)&u1.y);
        acc.x += d0 * v001.x + d1 * v101.x;
        acc.y += d0 * v001.y + d1 * v101.y;
        acc.z += d0 * v023.x + d1 * v123.x;
        acc.w += d0 * v023.y + d1 * v123.y;
    }
    if (j < c) {
        int s0 = g_src[o + j];
        float d0 = g_dinv[s0];
        uint2 u0 = ((const uint2*)(g_xt + (size_t)s0 * OUTD))[lane];
        float2 v01 = __half22float2(*(half2*)&u0.x);
        float2 v23 = __half22float2(*(half2*)&u0.y);
        acc.x += d0 * v01.x; acc.y += d0 * v01.y; acc.z += d0 * v23.x; acc.w += d0 * v23.y;
    }

    float4 b = ((const float4*)&g_base[(size_t)node * OUTD])[lane];
    float4 out;
    out.x = b.x + di * acc.x;
    out.y = b.y + di * acc.y;
    out.z = b.z + di * acc.z;
    out.w = b.w + di * acc.w;
    ((float4*)&g_base[(size_t)node * OUTD])[lane] = out;  // in-place pre-BN

    int c4 = lane * 4;
    atomicAdd(&s_sum[c4 + 0], out.x);
    atomicAdd(&s_sum[c4 + 1], out.y);
    atomicAdd(&s_sum[c4 + 2], out.z);
    atomicAdd(&s_sum[c4 + 3], out.w);
    atomicAdd(&s_sq[c4 + 0], out.x * out.x);
    atomicAdd(&s_sq[c4 + 1], out.y * out.y);
    atomicAdd(&s_sq[c4 + 2], out.z * out.z);
    atomicAdd(&s_sq[c4 + 3], out.w * out.w);
    __syncthreads();
    if (t < OUTD) {
        atomicAdd(&g_sum[t], s_sum[t]);
        atomicAdd(&g_sq[t], s_sq[t]);
    }
}

// Final: BN params computed per-block (redundant, trivial) + normalize + ReLU.
__global__ __launch_bounds__(1024) void k_final(const float* __restrict__ gamma,
                                                const float* __restrict__ beta,
                                                float* __restrict__ out) {
    __shared__ float sscale[OUTD];
    __shared__ float sshift[OUTD];
    int t = threadIdx.x;
    if (t < OUTD) {
        float m = g_sum[t] * (1.0f / NN);
        float var = g_sq[t] * (1.0f / NN) - m * m;
        float sc = rsqrtf(var + BN_EPS) * gamma[t];
        sscale[t] = sc;
        sshift[t] = beta[t] - m * sc;
    }
    __syncthreads();

    int i = blockIdx.x * 1024 + t;   // over NN*32 float4s
    int c4 = (i & 31) * 4;
    float4 v = ((const float4*)g_base)[i];
    float4 r;
    r.x = fmaxf(fmaf(v.x, sscale[c4 + 0], sshift[c4 + 0]), 0.f);
    r.y = fmaxf(fmaf(v.y, sscale[c4 + 1], sshift[c4 + 1]), 0.f);
    r.z = fmaxf(fmaf(v.z, sscale[c4 + 2], sshift[c4 + 2]), 0.f);
    r.w = fmaxf(fmaf(v.w, sscale[c4 + 3], sshift[c4 + 3]), 0.f);
    ((float4*)out)[i] = r;
}

// ---------------- launch ----------------
extern "C" void kernel_launch(void* const* d_in, const int* in_sizes, int n_in,
                              void* d_out, int out_size) {
    const float* x     = (const float*)d_in[0];
    const int*   ei    = (const int*)d_in[1];
    const float* W     = (const float*)d_in[2];
    const float* bias  = (const float*)d_in[3];
    const float* skw   = (const float*)d_in[4];
    const float* gamma = (const float*)d_in[5];
    const float* beta  = (const float*)d_in[6];
    (void)in_sizes; (void)n_in; (void)out_size;

    k_zero<<<98, 1024>>>();
    k_hist_gemmW<<<HIST_BLKS + GEMM_TILES, 256>>>(ei, x, W);
    k_scan1<<<NBLK, SCAN_B>>>();
    k_scan23<<<NBLK, SCAN_B>>>();
    k_scatter_gemmS<<<HIST_BLKS + GEMM_TILES, 256>>>(ei, x, skw, bias);
    k_aggr<<<3125, 1024>>>();
    k_final<<<3125, 1024>>>(gamma, beta, (float*)d_out);
}